// round 14
// baseline (speedup 1.0000x reference)
#include <cuda_runtime.h>
#include <cuda_fp16.h>
#include <cstddef>
#include <cstdint>

#define NN    50000
#define EE    800000
#define IN_D  512
#define HID_D 256
#define LAT_D 128
#define SCB   196      // reset blocks (ceil(NN/256))
#define SSTR  40       // fp16 smem row stride in halves (80B)
#define ASTR  40       // fp32 A smem row stride in floats (160B)
#define CVW   768      // weight-convert blocks (196608/256)
#define G1BLK 782      // gemm1 blocks (2 x 391)
#define G2BLK 782      // gemm2 blocks (2 x 391)
#define G1SMEM (2*128*ASTR*4 + 2*128*SSTR*2)   // 61440 B

typedef unsigned int u32;

// ---- static device scratch (zero-init at load; reset at end of each call) ----
__device__ __align__(16) float  g_deg[NN];     // accumulates from 0; dis=rsqrt(deg+1)
__device__ __align__(16) float  g_dis[NN];
__device__ __align__(16) __half g_w1t[HID_D * IN_D];         // W1^T  [256][512]
__device__ __align__(16) __half g_wmut[LAT_D * HID_D];       // Wmu^T [128][256]
__device__ __align__(16) __half g_wlvt[LAT_D * HID_D];       // Wlv^T [128][256]
__device__ __align__(16) __half g_h1f[(size_t)NN * HID_D];   // x@W1 (fp16)
__device__ __align__(16) __half g_hidf[(size_t)NN * HID_D];  // relu(agg1+b1) (fp16)
__device__ __align__(16) __half g_aggf[(size_t)NN * HID_D];  // agg2 (fp16)
// CSR
__device__ int   g_cnt[NN];
__device__ int   g_rowptr[NN + 1];
__device__ int   g_srcs[EE];
__device__ __align__(8) float g_nrm2[EE];

// ---------------- helpers ----------------
__device__ __forceinline__ void mma16(float* d, const u32* a, const u32* b) {
    asm("mma.sync.aligned.m16n8k16.row.col.f32.f16.f16.f32 "
        "{%0,%1,%2,%3}, {%4,%5,%6,%7}, {%8,%9}, {%0,%1,%2,%3};"
        : "+f"(d[0]), "+f"(d[1]), "+f"(d[2]), "+f"(d[3])
        : "r"(a[0]), "r"(a[1]), "r"(a[2]), "r"(a[3]), "r"(b[0]), "r"(b[1]));
}
__device__ __forceinline__ void cpa16(u32 smem, const void* gp, int src_sz) {
    asm volatile("cp.async.ca.shared.global [%0], [%1], 16, %2;"
                 :: "r"(smem), "l"(gp), "r"(src_sz));
}
__device__ __forceinline__ void cpa_commit() {
    asm volatile("cp.async.commit_group;");
}
template<int N>
__device__ __forceinline__ void cpa_wait() {
    asm volatile("cp.async.wait_group %0;" :: "n"(N));
}
__device__ __forceinline__ u32 packh2(const float* p) {
    float2 v = *reinterpret_cast<const float2*>(p);
    __half2 h = __floats2half2_rn(v.x, v.y);
    return *reinterpret_cast<u32*>(&h);
}
__device__ __forceinline__ void unpack8(uint4 u, float* v) {
    float2 f0 = __half22float2(*reinterpret_cast<__half2*>(&u.x));
    float2 f1 = __half22float2(*reinterpret_cast<__half2*>(&u.y));
    float2 f2 = __half22float2(*reinterpret_cast<__half2*>(&u.z));
    float2 f3 = __half22float2(*reinterpret_cast<__half2*>(&u.w));
    v[0] = f0.x; v[1] = f0.y; v[2] = f1.x; v[3] = f1.y;
    v[4] = f2.x; v[5] = f2.y; v[6] = f3.x; v[7] = f3.y;
}

// ---------------- fat prep: W transpose->fp16 | deg/cnt hist ----------------
__global__ __launch_bounds__(256) void k_prep(
    const float* __restrict__ W1, const float* __restrict__ Wmu,
    const float* __restrict__ Wlv,
    const int* __restrict__ ei, const float* __restrict__ ea)
{
    int b = blockIdx.x;
    if (b < CVW) {
        int idx = b * 256 + threadIdx.x;
        if (idx < HID_D * IN_D) {                  // W1T[n][k] = W1[k][n]
            int n = idx >> 9, k = idx & 511;
            g_w1t[idx] = __float2half(W1[k * HID_D + n]);
        } else {
            int j = idx - HID_D * IN_D;            // 2 x 32768 for Wmu/Wlv
            int which = j >= LAT_D * HID_D;
            int jj = j - which * LAT_D * HID_D;
            int n = jj >> 8, k = jj & 255;
            const float* W = which ? Wlv : Wmu;
            (which ? g_wlvt : g_wmut)[jj] = __float2half(W[k * LAT_D + n]);
        }
    } else {
        int e = (b - CVW) * 256 + threadIdx.x;
        if (e < EE) {
            int d = ei[EE + e];
            atomicAdd(&g_deg[d], ea[e]);
            atomicAdd(&g_cnt[d], 1);
        }
    }
}

// ---------------- single-block scan: rowptr/cursor/dis ----------------
#define SCHUNK 49   // 1024*49 = 50176 >= NN
__global__ __launch_bounds__(1024) void k_scan_all() {
    __shared__ int s[1024];
    int t = threadIdx.x;
    int base = t * SCHUNK;
    int sum = 0;
    #pragma unroll 7
    for (int i = 0; i < SCHUNK; i++) {
        int idx = base + i;
        if (idx < NN) sum += g_cnt[idx];
    }
    s[t] = sum;
    #pragma unroll
    for (int off = 1; off < 1024; off <<= 1) {
        __syncthreads();
        int a = (t >= off) ? s[t - off] : 0;
        __syncthreads();
        s[t] += a;
    }
    __syncthreads();
    int run = (t > 0) ? s[t - 1] : 0;
    #pragma unroll 7
    for (int i = 0; i < SCHUNK; i++) {
        int idx = base + i;
        if (idx < NN) {
            int c = g_cnt[idx];
            g_rowptr[idx] = run;
            g_cnt[idx] = run;                       // cursor for fill
            g_dis[idx] = rsqrtf(g_deg[idx] + 1.0f); // self-loop weight 1
            run += c;
        }
    }
    if (t == 0) g_rowptr[NN] = EE;
}

// ---------------- gemm1: fp32-A HMMA (128x128 tile, BK=32, dyn smem) ----------------
// g_h1f[NN,256](fp16) = x[NN,512](fp32) @ W1T^T
__device__ __forceinline__ void gemm1_body(int bx, int by, const float* __restrict__ x) {
    extern __shared__ __align__(16) char dynsm[];
    float*  Asf = reinterpret_cast<float*>(dynsm);                      // 2 x 128 x ASTR
    __half* Bsh = reinterpret_cast<__half*>(dynsm + 2 * 128 * ASTR * 4); // 2 x 128 x SSTR

    const int K = IN_D;
    const int M = NN;
    int nBase = bx * 128;
    int mBase = by * 128;

    int tid = threadIdx.x;
    int lane = tid & 31;
    int wid = tid >> 5;
    int warp_m = wid >> 1;
    int warp_n = wid & 1;
    int g = lane >> 2;
    int l = lane & 3;

    int c_row = tid >> 1;              // 0..127
    int half = tid & 1;                // A: 16-float half-row; B: 16-half half-row

    u32 sA = (u32)__cvta_generic_to_shared(Asf);
    u32 sB = (u32)__cvta_generic_to_shared(Bsh);
    const u32 A_STG = 128 * ASTR * 4;
    const u32 B_STG = 128 * SSTR * 2;

    int a_sz = (mBase + c_row < M) ? 16 : 0;
    const __half* Bt = g_w1t;
    const int KT = K >> 5;

    // prologue: tile 0
    {
        const float* ga = x + (size_t)(mBase + c_row) * K + half * 16;
        u32 da = sA + (c_row * ASTR + half * 16) * 4;
        cpa16(da,      ga,      a_sz);
        cpa16(da + 16, ga + 4,  a_sz);
        cpa16(da + 32, ga + 8,  a_sz);
        cpa16(da + 48, ga + 12, a_sz);
        const __half* gb = Bt + (size_t)(nBase + c_row) * K + half * 16;
        u32 db = sB + (c_row * SSTR + half * 16) * 2;
        cpa16(db,      gb,     16);
        cpa16(db + 16, gb + 8, 16);
        cpa_commit();
    }

    float acc[2][8][4];
    #pragma unroll
    for (int mi = 0; mi < 2; mi++)
        #pragma unroll
        for (int ni = 0; ni < 8; ni++)
            #pragma unroll
            for (int q = 0; q < 4; q++) acc[mi][ni][q] = 0.0f;

    for (int kt = 0; kt < KT; kt++) {
        int st = kt & 1;
        if (kt + 1 < KT) {
            int ns = (kt + 1) & 1;
            int k0 = (kt + 1) << 5;
            const float* ga = x + (size_t)(mBase + c_row) * K + k0 + half * 16;
            u32 da = sA + ns * A_STG + (c_row * ASTR + half * 16) * 4;
            cpa16(da,      ga,      a_sz);
            cpa16(da + 16, ga + 4,  a_sz);
            cpa16(da + 32, ga + 8,  a_sz);
            cpa16(da + 48, ga + 12, a_sz);
            const __half* gb = Bt + (size_t)(nBase + c_row) * K + k0 + half * 16;
            u32 db = sB + ns * B_STG + (c_row * SSTR + half * 16) * 2;
            cpa16(db,      gb,     16);
            cpa16(db + 16, gb + 8, 16);
            cpa_commit();
            cpa_wait<1>();
        } else {
            cpa_wait<0>();
        }
        __syncthreads();

        const float* Af = Asf + st * 128 * ASTR;
        const u32*   Bu = reinterpret_cast<const u32*>(Bsh + st * 128 * SSTR);
        const int RS = SSTR >> 1;   // 20 u32 per B row

        #pragma unroll
        for (int ks = 0; ks < 2; ks++) {
            int kf = (ks << 4) + (l << 1);   // float k-offset
            u32 af[2][4];
            #pragma unroll
            for (int mi = 0; mi < 2; mi++) {
                int r0 = warp_m * 32 + mi * 16 + g;
                af[mi][0] = packh2(Af + r0 * ASTR + kf);
                af[mi][1] = packh2(Af + (r0 + 8) * ASTR + kf);
                af[mi][2] = packh2(Af + r0 * ASTR + kf + 8);
                af[mi][3] = packh2(Af + (r0 + 8) * ASTR + kf + 8);
            }
            int ko = ks << 3;
            u32 bf[8][2];
            #pragma unroll
            for (int ni = 0; ni < 8; ni++) {
                int base = (warp_n * 64 + ni * 8 + g) * RS + ko + l;
                bf[ni][0] = Bu[base];
                bf[ni][1] = Bu[base + 4];
            }
            #pragma unroll
            for (int mi = 0; mi < 2; mi++)
                #pragma unroll
                for (int ni = 0; ni < 8; ni++)
                    mma16(acc[mi][ni], af[mi], bf[ni]);
        }
        __syncthreads();
    }

    // epilogue -> fp16 h1
    #pragma unroll
    for (int mi = 0; mi < 2; mi++) {
        int r0 = mBase + warp_m * 32 + mi * 16 + g;
        int r1 = r0 + 8;
        #pragma unroll
        for (int ni = 0; ni < 8; ni++) {
            int col = nBase + warp_n * 64 + ni * 8 + (l << 1);
            if (r0 < M)
                *reinterpret_cast<__half2*>(g_h1f + (size_t)r0 * HID_D + col) =
                    __floats2half2_rn(acc[mi][ni][0], acc[mi][ni][1]);
            if (r1 < M)
                *reinterpret_cast<__half2*>(g_h1f + (size_t)r1 * HID_D + col) =
                    __floats2half2_rn(acc[mi][ni][2], acc[mi][ni][3]);
        }
    }
}

// ---------------- gemm2: fp16 HMMA (existing proven path) ----------------
// out[NN,128] = aggf[NN,256] @ W?T^T + bias
__device__ __forceinline__ void gemm2_body(
    int bx, int by, const float* __restrict__ bias, float* __restrict__ out)
{
    const __half* A = g_aggf;
    const __half* Bt = bx ? g_wlvt : g_wmut;
    const int K = HID_D;
    const int M = NN;
    int mBase = by * 128;

    __shared__ __half As[2][128][SSTR];
    __shared__ __half Bs[2][128][SSTR];

    int tid = threadIdx.x;
    int lane = tid & 31;
    int wid = tid >> 5;
    int warp_m = wid >> 1;
    int warp_n = wid & 1;
    int g = lane >> 2;
    int l = lane & 3;

    int c_row = tid >> 1;
    int c_off = (tid & 1) << 4;

    u32 sA = (u32)__cvta_generic_to_shared(&As[0][0][0]);
    u32 sB = (u32)__cvta_generic_to_shared(&Bs[0][0][0]);
    const u32 STG = 128 * SSTR * 2;

    int a_sz = (mBase + c_row < M) ? 16 : 0;
    const int KT = K >> 5;

    cpa16(sA + (c_row * SSTR + c_off) * 2,     A + (size_t)(mBase + c_row) * K + c_off, a_sz);
    cpa16(sA + (c_row * SSTR + c_off + 8) * 2, A + (size_t)(mBase + c_row) * K + c_off + 8, a_sz);
    cpa16(sB + (c_row * SSTR + c_off) * 2,     Bt + (size_t)c_row * K + c_off, 16);
    cpa16(sB + (c_row * SSTR + c_off + 8) * 2, Bt + (size_t)c_row * K + c_off + 8, 16);
    cpa_commit();

    float acc[2][8][4];
    #pragma unroll
    for (int mi = 0; mi < 2; mi++)
        #pragma unroll
        for (int ni = 0; ni < 8; ni++)
            #pragma unroll
            for (int q = 0; q < 4; q++) acc[mi][ni][q] = 0.0f;

    for (int kt = 0; kt < KT; kt++) {
        int st = kt & 1;
        if (kt + 1 < KT) {
            int ns = (kt + 1) & 1;
            int k0 = (kt + 1) << 5;
            cpa16(sA + ns * STG + (c_row * SSTR + c_off) * 2,
                  A + (size_t)(mBase + c_row) * K + k0 + c_off, a_sz);
            cpa16(sA + ns * STG + (c_row * SSTR + c_off + 8) * 2,
                  A + (size_t)(mBase + c_row) * K + k0 + c_off + 8, a_sz);
            cpa16(sB + ns * STG + (c_row * SSTR + c_off) * 2,
                  Bt + (size_t)c_row * K + k0 + c_off, 16);
            cpa16(sB + ns * STG + (c_row * SSTR + c_off + 8) * 2,
                  Bt + (size_t)c_row * K + k0 + c_off + 8, 16);
            cpa_commit();
            cpa_wait<1>();
        } else {
            cpa_wait<0>();
        }
        __syncthreads();

        const u32* Au = reinterpret_cast<const u32*>(&As[st][0][0]);
        const u32* Bu = reinterpret_cast<const u32*>(&Bs[st][0][0]);
        const int RS = SSTR >> 1;

        #pragma unroll
        for (int ks = 0; ks < 2; ks++) {
            int ko = ks << 3;
            u32 af[2][4];
            #pragma unroll
            for (int mi = 0; mi < 2; mi++) {
                int base = (warp_m * 32 + mi * 16 + g) * RS + ko + l;
                af[mi][0] = Au[base];
                af[mi][1] = Au[base + 8 * RS];
                af[mi][2] = Au[base + 4];
                af[mi][3] = Au[base + 8 * RS + 4];
            }
            u32 bf[8][2];
            #pragma unroll
            for (int ni = 0; ni < 8; ni++) {
                int base = (warp_n * 64 + ni * 8 + g) * RS + ko + l;
                bf[ni][0] = Bu[base];
                bf[ni][1] = Bu[base + 4];
            }
            #pragma unroll
            for (int mi = 0; mi < 2; mi++)
                #pragma unroll
                for (int ni = 0; ni < 8; ni++)
                    mma16(acc[mi][ni], af[mi], bf[ni]);
        }
        __syncthreads();
    }

    #pragma unroll
    for (int mi = 0; mi < 2; mi++) {
        int r0 = mBase + warp_m * 32 + mi * 16 + g;
        int r1 = r0 + 8;
        #pragma unroll
        for (int ni = 0; ni < 8; ni++) {
            int col = warp_n * 64 + ni * 8 + (l << 1);
            float2 bb = *reinterpret_cast<const float2*>(bias + col);
            if (r0 < M) {
                float2 o; o.x = acc[mi][ni][0] + bb.x; o.y = acc[mi][ni][1] + bb.y;
                *reinterpret_cast<float2*>(out + (size_t)r0 * LAT_D + col) = o;
            }
            if (r1 < M) {
                float2 o; o.x = acc[mi][ni][2] + bb.x; o.y = acc[mi][ni][3] + bb.y;
                *reinterpret_cast<float2*>(out + (size_t)r1 * LAT_D + col) = o;
            }
        }
    }
}

// ---------------- fat: gemm1 + CSR fill ----------------
__global__ __launch_bounds__(256) void k_gemm1_fill(
    const float* __restrict__ x,
    const int* __restrict__ ei, const float* __restrict__ ea)
{
    if (blockIdx.x < G1BLK) {
        gemm1_body(blockIdx.x & 1, blockIdx.x >> 1, x);
    } else {
        int e = (blockIdx.x - G1BLK) * 256 + threadIdx.x;
        if (e < EE) {
            int s = ei[e];
            int d = ei[EE + e];
            int pos = atomicAdd(&g_cnt[d], 1);
            g_srcs[pos] = s;
            g_nrm2[pos] = g_dis[s] * ea[e] * g_dis[d];
        }
    }
}

// ---------------- fat: gemm2 (mu/logvar) + scratch reset ----------------
__global__ __launch_bounds__(256) void k_gemm2_reset(
    const float* __restrict__ bmu, const float* __restrict__ blv,
    float* __restrict__ out)
{
    if (blockIdx.x < G2BLK) {
        int bx = blockIdx.x & 1;
        gemm2_body(bx, blockIdx.x >> 1, bx ? blv : bmu,
                   out + (size_t)bx * NN * LAT_D);
    } else {
        int i = (blockIdx.x - G2BLK) * 256 + threadIdx.x;
        if (i < NN) { g_deg[i] = 0.0f; g_cnt[i] = 0; }
    }
}

// ---------------- gather aggregation (fp16 features, fp32 accumulate) ----------------
// PHASE 0: feat = g_h1f;  out = g_hidf = relu(agg + b1)  (fp16)
// PHASE 1: feat = g_hidf; out = g_aggf (fp16)
template<int PHASE>
__global__ __launch_bounds__(256) void k_gather(const float* __restrict__ b1) {
    int node = (blockIdx.x << 3) + (threadIdx.x >> 5);
    if (node >= NN) return;
    int c = (threadIdx.x & 31) << 3;
    const __half* feat = (PHASE == 0) ? g_h1f : g_hidf;

    float ds = g_dis[node];
    float dsq = ds * ds;
    float acc[8], v[8];
    {
        uint4 u = *reinterpret_cast<const uint4*>(feat + (size_t)node * HID_D + c);
        unpack8(u, v);
        #pragma unroll
        for (int i = 0; i < 8; i++) acc[i] = dsq * v[i];
    }

    int beg = g_rowptr[node];
    int end = g_rowptr[node + 1];
    int j = beg;
    for (; j + 1 < end; j += 2) {
        int   s0 = __ldg(&g_srcs[j]);
        int   s1 = __ldg(&g_srcs[j + 1]);
        float n0 = __ldg(&g_nrm2[j]);
        float n1 = __ldg(&g_nrm2[j + 1]);
        uint4 u0 = *reinterpret_cast<const uint4*>(feat + (size_t)s0 * HID_D + c);
        uint4 u1 = *reinterpret_cast<const uint4*>(feat + (size_t)s1 * HID_D + c);
        float w0[8], w1[8];
        unpack8(u0, w0);
        unpack8(u1, w1);
        #pragma unroll
        for (int i = 0; i < 8; i++) acc[i] = fmaf(w0[i], n0, acc[i]);
        #pragma unroll
        for (int i = 0; i < 8; i++) acc[i] = fmaf(w1[i], n1, acc[i]);
    }
    if (j < end) {
        int   s0 = __ldg(&g_srcs[j]);
        float n0 = __ldg(&g_nrm2[j]);
        uint4 u0 = *reinterpret_cast<const uint4*>(feat + (size_t)s0 * HID_D + c);
        float w0[8];
        unpack8(u0, w0);
        #pragma unroll
        for (int i = 0; i < 8; i++) acc[i] = fmaf(w0[i], n0, acc[i]);
    }

    uint4 u;
    if (PHASE == 0) {
        float4 bb0 = *reinterpret_cast<const float4*>(b1 + c);
        float4 bb1 = *reinterpret_cast<const float4*>(b1 + c + 4);
        float h[8];
        h[0] = fmaxf(acc[0] + bb0.x, 0.0f); h[1] = fmaxf(acc[1] + bb0.y, 0.0f);
        h[2] = fmaxf(acc[2] + bb0.z, 0.0f); h[3] = fmaxf(acc[3] + bb0.w, 0.0f);
        h[4] = fmaxf(acc[4] + bb1.x, 0.0f); h[5] = fmaxf(acc[5] + bb1.y, 0.0f);
        h[6] = fmaxf(acc[6] + bb1.z, 0.0f); h[7] = fmaxf(acc[7] + bb1.w, 0.0f);
        *reinterpret_cast<__half2*>(&u.x) = __floats2half2_rn(h[0], h[1]);
        *reinterpret_cast<__half2*>(&u.y) = __floats2half2_rn(h[2], h[3]);
        *reinterpret_cast<__half2*>(&u.z) = __floats2half2_rn(h[4], h[5]);
        *reinterpret_cast<__half2*>(&u.w) = __floats2half2_rn(h[6], h[7]);
        *reinterpret_cast<uint4*>(g_hidf + (size_t)node * HID_D + c) = u;
    } else {
        *reinterpret_cast<__half2*>(&u.x) = __floats2half2_rn(acc[0], acc[1]);
        *reinterpret_cast<__half2*>(&u.y) = __floats2half2_rn(acc[2], acc[3]);
        *reinterpret_cast<__half2*>(&u.z) = __floats2half2_rn(acc[4], acc[5]);
        *reinterpret_cast<__half2*>(&u.w) = __floats2half2_rn(acc[6], acc[7]);
        *reinterpret_cast<uint4*>(g_aggf + (size_t)node * HID_D + c) = u;
    }
}

// ---------------- launch ----------------
extern "C" void kernel_launch(void* const* d_in, const int* in_sizes, int n_in,
                              void* d_out, int out_size) {
    const float* x   = (const float*)d_in[0];
    const int*   ei  = (const int*)d_in[1];     // [2, E] int32
    const float* ea  = (const float*)d_in[2];
    const float* W1  = (const float*)d_in[3];
    const float* b1  = (const float*)d_in[4];
    const float* Wmu = (const float*)d_in[5];
    const float* bmu = (const float*)d_in[6];
    const float* Wlv = (const float*)d_in[7];
    const float* blv = (const float*)d_in[8];
    float* out = (float*)d_out;

    const int TB = 256;
    int gE = (EE + TB - 1) / TB;   // 3125

    static bool attr_done = false;
    if (!attr_done) {
        cudaFuncSetAttribute(k_gemm1_fill,
                             cudaFuncAttributeMaxDynamicSharedMemorySize, G1SMEM);
        attr_done = true;
    }

    // ---- prep: W->fp16 transposed | deg/cnt histogram ----
    k_prep<<<CVW + gE, TB>>>(W1, Wmu, Wlv, ei, ea);

    // ---- single-block scan (+dis) ----
    k_scan_all<<<1, 1024>>>();

    // ---- fat: conv1 transform (fp32-A HMMA) + CSR fill ----
    k_gemm1_fill<<<G1BLK + gE, 256, G1SMEM>>>(x, ei, ea);

    // ---- aggregate conv1 (+bias+relu) / conv2 ----
    int gG = (NN + 7) / 8;
    k_gather<0><<<gG, 256>>>(b1);
    k_gather<1><<<gG, 256>>>(b1);

    // ---- fat: mu / logvar GEMMs + scratch reset ----
    k_gemm2_reset<<<G2BLK + SCB, 256>>>(bmu, blv, out);
}